// round 13
// baseline (speedup 1.0000x reference)
#include <cuda_runtime.h>
#include <stdint.h>

// preds: [32, 3, 640, 640] fp32
#define B_     32
#define H_     640
#define W_     640
#define HW_    (H_ * W_)          // 409600 floats per channel
#define TOPK_  1000
#define NB2    2048               // sort buckets
#define CAP    4096
#define TG     2.6f               // static fast-path threshold (p~0.0047 -> ~1900/img)
#define BX     100                // pass blocks per image (4096 floats each)
#define TPB    256
#define STAGE  1024

typedef unsigned long long ull;

// Device scratch (zero at load; k_select restores g_count each execution)
__device__ ull    g_cand[B_ * CAP];
__device__ float2 g_hw[B_ * CAP];    // (ph[idx], pw[idx]) per candidate slot
__device__ ull    g_sorted[B_ * CAP];
__device__ int    g_count[B_];

// Order-preserving bijection float -> uint (monotone increasing)
__device__ __forceinline__ unsigned int ordf(float x) {
    unsigned int u = __float_as_uint(x);
    return (u & 0x80000000u) ? ~u : (u | 0x80000000u);
}

// ---------------------------------------------------------------------------
// Kernel A: streaming pass (structure identical to 23.0us champion) + per-hit
// gather of ph/pw into a compact side array (hidden by 3200-block parallelism).
// ---------------------------------------------------------------------------
__global__ void __launch_bounds__(TPB) k_pass(const float* __restrict__ preds) {
    __shared__ __align__(16) ull    stage[STAGE];   // 8 KB
    __shared__ __align__(8)  float2 hwst[STAGE];    // 8 KB
    __shared__ int sh_cnt, sh_base, sh_ovf;

    const int b = blockIdx.y;
    const int t = threadIdx.x;
    const int lane = t & 31;

    if (t == 0) { sh_cnt = 0; sh_ovf = 0; }
    __syncthreads();

    const float* __restrict__ chan = preds + (size_t)b * 3 * HW_;
    const float4* __restrict__ sc = (const float4*)chan;
    const int tid = blockIdx.x * TPB + t;   // 0..25599

    float4 v[4];
#pragma unroll
    for (int j = 0; j < 4; j++) v[j] = sc[tid + j * 25600];

    float mx = v[0].x;
#pragma unroll
    for (int j = 0; j < 4; j++) {
        mx = fmaxf(mx, fmaxf(fmaxf(v[j].x, v[j].y), fmaxf(v[j].z, v[j].w)));
    }

    unsigned int m = 0;
    if (mx >= TG) {
#pragma unroll
        for (int j = 0; j < 4; j++) {
            m |= (v[j].x >= TG) ? (1u << (4 * j + 0)) : 0u;
            m |= (v[j].y >= TG) ? (1u << (4 * j + 1)) : 0u;
            m |= (v[j].z >= TG) ? (1u << (4 * j + 2)) : 0u;
            m |= (v[j].w >= TG) ? (1u << (4 * j + 3)) : 0u;
        }
    }

    const int nh = __popc(m);
    if (__ballot_sync(0xFFFFFFFFu, nh) != 0) {
        int pre = nh;
#pragma unroll
        for (int off = 1; off < 32; off <<= 1) {
            int y = __shfl_up_sync(0xFFFFFFFFu, pre, off);
            if (lane >= off) pre += y;
        }
        const int tot = __shfl_sync(0xFFFFFFFFu, pre, 31);
        int wbase = 0;
        if (lane == 31) wbase = atomicAdd(&sh_cnt, tot);
        wbase = __shfl_sync(0xFFFFFFFFu, wbase, 31);

        int pos = wbase + pre - nh;
        if (nh) {
#pragma unroll
            for (int j = 0; j < 4; j++) {
                const int i4 = tid + j * 25600;
                const float f0 = v[j].x, f1 = v[j].y, f2 = v[j].z, f3 = v[j].w;
#pragma unroll
                for (int k = 0; k < 4; k++) {
                    if (m & (1u << (4 * j + k))) {
                        if (pos < STAGE) {
                            const float f = (k == 0) ? f0 : (k == 1) ? f1 : (k == 2) ? f2 : f3;
                            const unsigned int o = ordf(f);
                            const unsigned int idx = (unsigned int)(i4 * 4 + k);
                            stage[pos] = ((ull)o << 32) | (ull)(0xFFFFFFFFu - idx);
                            // per-hit gather of raw h/w values (latency-hidden)
                            hwst[pos] = make_float2(__ldg(&chan[HW_ + idx]),
                                                    __ldg(&chan[2 * HW_ + idx]));
                        } else {
                            sh_ovf = 1;
                        }
                        pos++;
                    }
                }
            }
        }
    }
    __syncthreads();

    if (t == 0) {
        int add = sh_cnt + (sh_ovf ? 1000000 : 0);   // poison on overflow
        sh_base = add ? atomicAdd(&g_count[b], add) : 0;
    }
    __syncthreads();

    const int cnt = min(sh_cnt, STAGE);
    const int base = sh_base;
    for (int i = t; i < cnt; i += TPB) {
        const int p = base + i;
        if (p < CAP) {
            g_cand[b * CAP + p] = stage[i];
            g_hw[b * CAP + p]   = hwst[i];
        }
    }
}

// ---------------------------------------------------------------------------
// Kernel B: per-image select. grid 32 x 1024. Counting sort in shared with a
// parallel slot array; emit reads h/w from the compact g_hw (no random DRAM
// gather). Fallback / M>2048 paths emit via direct gather (correct, unused).
// ---------------------------------------------------------------------------
__global__ void __launch_bounds__(1024) k_select(const float* __restrict__ preds,
                                                 float* __restrict__ out) {
    __shared__ __align__(16) ull skeys[2048];        // 16 KB raw keys
    __shared__ __align__(16) ull ssort[2048];        // 16 KB sorted keys
    __shared__ unsigned short sslot[2048];           //  4 KB sorted slots
    __shared__ unsigned int hist[NB2];               //  8 KB
    __shared__ unsigned int start[NB2];              //  8 KB
    __shared__ unsigned int part[1024];              //  4 KB (fallback only)
    __shared__ unsigned int wtmp[32], wtmp2[32];
    __shared__ unsigned int sh_mn, sh_sh;
    __shared__ int sh_T, sh_c2;

    const int b = blockIdx.x;
    const int t = threadIdx.x;
    const int lane = t & 31;
    const int wid = t >> 5;

    const float* chan = preds + (size_t)b * 3 * HW_;

    int M = g_count[b];
    bool fb = false;

    // ============ FALLBACK (never taken for valid fast path) ============
    if (M < TOPK_ || M > CAP) {
        fb = true;
        for (int i = t; i < NB2; i += 1024) hist[i] = 0u;
        if (t == 0) { sh_T = 0; sh_c2 = 0; }
        __syncthreads();

        const float4* sc = (const float4*)chan;
        for (int i = t; i < HW_ / 4; i += 1024) {
            const float4 w = sc[i];
            atomicAdd(&hist[ordf(w.x) >> 21], 1u);
            atomicAdd(&hist[ordf(w.y) >> 21], 1u);
            atomicAdd(&hist[ordf(w.z) >> 21], 1u);
            atomicAdd(&hist[ordf(w.w) >> 21], 1u);
        }
        __syncthreads();

        const unsigned int p2 = hist[2 * t] + hist[2 * t + 1];
        part[t] = p2;
        __syncthreads();
        for (int off = 1; off < 1024; off <<= 1) {
            unsigned int vv = (t + off < 1024) ? part[t + off] : 0u;
            __syncthreads();
            part[t] += vv;
            __syncthreads();
        }
        unsigned int acc = part[t] - p2;
        for (int j = 1; j >= 0; j--) {
            acc += hist[2 * t + j];
            if (acc >= (unsigned)TOPK_) { atomicMax(&sh_T, 2 * t + j); break; }
        }
        __syncthreads();
        const unsigned int T = (unsigned int)sh_T;

        for (int i = t; i < HW_ / 4; i += 1024) {
            const float4 w = sc[i];
            const float f[4] = {w.x, w.y, w.z, w.w};
#pragma unroll
            for (int k = 0; k < 4; k++) {
                const unsigned int o = ordf(f[k]);
                if ((o >> 21) >= T) {
                    const int p = atomicAdd(&sh_c2, 1);
                    if (p < CAP) {
                        const unsigned int idx = (unsigned int)(i * 4 + k);
                        g_cand[b * CAP + p] = ((ull)o << 32) | (ull)(0xFFFFFFFFu - idx);
                    }
                }
            }
        }
        __syncthreads();
        M = min(sh_c2, CAP);
    }
    M = min(M, CAP);

    const bool inshared = (M <= 2048);
    const bool useHw = inshared && !fb;                  // g_hw valid & slots carried
    ull* kraw = inshared ? skeys : &g_cand[b * CAP];
    ull* kbuf = inshared ? ssort : &g_sorted[b * CAP];

    // ---- load keys to shared once + min/max (fused) ----
    unsigned int lmin = 0xFFFFFFFFu, lmax = 0u;
    for (int i = t; i < M; i += 1024) {
        const ull key = g_cand[b * CAP + i];
        if (inshared) skeys[i] = key;
        const unsigned int h = (unsigned int)(key >> 32);
        lmin = min(lmin, h);
        lmax = max(lmax, h);
    }
#pragma unroll
    for (int off = 16; off > 0; off >>= 1) {
        lmin = min(lmin, __shfl_down_sync(0xFFFFFFFFu, lmin, off));
        lmax = max(lmax, __shfl_down_sync(0xFFFFFFFFu, lmax, off));
    }
    if (lane == 0) { wtmp[wid] = lmin; wtmp2[wid] = lmax; }
    hist[2 * t] = 0u; hist[2 * t + 1] = 0u;
    __syncthreads();
    if (wid == 0) {
        unsigned int mn = wtmp[lane], mx = wtmp2[lane];
#pragma unroll
        for (int off = 16; off > 0; off >>= 1) {
            mn = min(mn, __shfl_down_sync(0xFFFFFFFFu, mn, off));
            mx = max(mx, __shfl_down_sync(0xFFFFFFFFu, mx, off));
        }
        if (lane == 0) {
            const unsigned int range = mx - mn;
            const int bits = 32 - __clz(range | 1u);
            sh_sh = (bits > 11) ? (unsigned)(bits - 11) : 0u;
            sh_mn = mn;
        }
    }
    __syncthreads();
    const unsigned int mn = sh_mn, shf = sh_sh;

    // ---- histogram ----
    for (int i = t; i < M; i += 1024) {
        const unsigned int h = (unsigned int)(kraw[i] >> 32);
        atomicAdd(&hist[(h - mn) >> shf], 1u);
    }
    __syncthreads();

    // ---- hierarchical suffix scan over 2048 buckets ----
    const unsigned int h0 = hist[2 * t], h1 = hist[2 * t + 1];
    const unsigned int s_own = h0 + h1;
    unsigned int s_incl = s_own;
#pragma unroll
    for (int off = 1; off < 32; off <<= 1) {
        unsigned int y = __shfl_down_sync(0xFFFFFFFFu, s_incl, off);
        if (lane + off < 32) s_incl += y;
    }
    if (lane == 0) wtmp[wid] = s_incl;
    __syncthreads();
    if (wid == 0) {
        unsigned int wv = wtmp[lane];
        unsigned int wincl = wv;
#pragma unroll
        for (int off = 1; off < 32; off <<= 1) {
            unsigned int y = __shfl_down_sync(0xFFFFFFFFu, wincl, off);
            if (lane + off < 32) wincl += y;
        }
        wtmp[lane] = wincl - wv;
    }
    __syncthreads();
    {
        const unsigned int above = wtmp[wid] + (s_incl - s_own);
        start[2 * t + 1] = above;
        start[2 * t]     = above + h1;
        hist[2 * t] = 0u; hist[2 * t + 1] = 0u;
    }
    __syncthreads();

    // ---- scatter (keys + slots) ----
    for (int i = t; i < M; i += 1024) {
        const ull key = kraw[i];
        const unsigned int bk = ((unsigned int)(key >> 32) - mn) >> shf;
        const unsigned int p = start[bk] + atomicAdd(&hist[bk], 1u);
        kbuf[p] = key;
        if (useHw) sslot[p] = (unsigned short)i;
    }
    __syncthreads();

    // ---- per-bucket insertion sort (descending) for buckets touching [0, TOPK) ----
    for (int bk = t; bk < NB2; bk += 1024) {
        const unsigned int c = hist[bk];
        if (c > 1u && start[bk] < (unsigned)TOPK_) {
            ull* s2 = &kbuf[start[bk]];
            if (useHw) {
                unsigned short* l2 = &sslot[start[bk]];
                for (unsigned int a = 1; a < c; a++) {
                    const ull kv = s2[a];
                    const unsigned short lv = l2[a];
                    int q = (int)a - 1;
                    while (q >= 0 && s2[q] < kv) {
                        s2[q + 1] = s2[q]; l2[q + 1] = l2[q]; q--;
                    }
                    s2[q + 1] = kv; l2[q + 1] = lv;
                }
            } else {
                for (unsigned int a = 1; a < c; a++) {
                    const ull kv = s2[a];
                    int q = (int)a - 1;
                    while (q >= 0 && s2[q] < kv) { s2[q + 1] = s2[q]; q--; }
                    s2[q + 1] = kv;
                }
            }
        }
    }
    __syncthreads();

    // ---- emit ----
    const float* ph = chan + HW_;
    const float* pw = ph + HW_;
    float* boxes  = out;                              // [B, K, 4]
    float* scores = out + (size_t)B_ * TOPK_ * 4;     // [B, K]
    float* keep   = scores + (size_t)B_ * TOPK_;      // [B, K]

    if (t < TOPK_) {
        const ull kk = kbuf[t];
        const unsigned int o = (unsigned int)(kk >> 32);
        const unsigned int u = (o & 0x80000000u) ? (o ^ 0x80000000u) : ~o;
        const float score = __uint_as_float(u);
        const unsigned int idx = 0xFFFFFFFFu - (unsigned int)(kk & 0xFFFFFFFFull);

        float hraw, wraw;
        if (useHw) {
            const float2 hw = g_hw[b * CAP + sslot[t]];
            hraw = hw.x; wraw = hw.y;
        } else {
            hraw = ph[idx]; wraw = pw[idx];
        }
        const float h = fmaxf(hraw, 1e-6f) * (float)H_;
        const float w = fmaxf(wraw, 1e-6f) * (float)W_;
        const float cx = (float)(idx % W_);
        const float cy = (float)(idx / W_);

        float* bx = boxes + ((size_t)b * TOPK_ + t) * 4;
        bx[0] = cx - 0.5f * w;
        bx[1] = cy - 0.5f * h;
        bx[2] = cx + 0.5f * w;
        bx[3] = cy + 0.5f * h;
        scores[b * TOPK_ + t] = score;
        keep[b * TOPK_ + t]   = 1.0f;
    }

    if (t == 0) g_count[b] = 0;   // reset for next graph replay
}

// ---------------------------------------------------------------------------
extern "C" void kernel_launch(void* const* d_in, const int* in_sizes, int n_in,
                              void* d_out, int out_size) {
    const float* preds = (const float*)d_in[0];
    float* out = (float*)d_out;

    dim3 gp(BX, B_);
    k_pass<<<gp, TPB>>>(preds);
    k_select<<<B_, 1024>>>(preds, out);
}

// round 14
// speedup vs baseline: 1.2911x; 1.2911x over previous
#include <cuda_runtime.h>
#include <stdint.h>

// preds: [32, 3, 640, 640] fp32
#define B_     32
#define H_     640
#define W_     640
#define HW_    (H_ * W_)          // 409600 floats per channel
#define TOPK_  1000
#define NB2    2048               // sort buckets
#define CAP    4096
#define TG     2.6f               // static fast-path threshold (p~0.0047 -> ~1900/img)
#define BX     100                // pass blocks per image (4096 floats each)
#define TPB    256
#define STAGE  1024

typedef unsigned long long ull;

// Device scratch (zero at load; k_select restores g_count each execution)
__device__ ull g_cand[B_ * CAP];
__device__ ull g_sorted[B_ * CAP];   // only used when M > 2048
__device__ int g_count[B_];

// Order-preserving bijection float -> uint (monotone increasing)
__device__ __forceinline__ unsigned int ordf(float x) {
    unsigned int u = __float_as_uint(x);
    return (u & 0x80000000u) ? ~u : (u | 0x80000000u);
}

// ---------------------------------------------------------------------------
// Kernel A: streaming pass — bit-identical to the 23.0us champion.
// ---------------------------------------------------------------------------
__global__ void __launch_bounds__(TPB) k_pass(const float* __restrict__ preds) {
    __shared__ __align__(16) ull stage[STAGE];   // 8 KB
    __shared__ int sh_cnt, sh_base, sh_ovf;

    const int b = blockIdx.y;
    const int t = threadIdx.x;
    const int lane = t & 31;

    if (t == 0) { sh_cnt = 0; sh_ovf = 0; }
    __syncthreads();

    const float4* __restrict__ sc = (const float4*)(preds + (size_t)b * 3 * HW_);
    const int tid = blockIdx.x * TPB + t;   // 0..25599

    float4 v[4];
#pragma unroll
    for (int j = 0; j < 4; j++) v[j] = sc[tid + j * 25600];

    float mx = v[0].x;
#pragma unroll
    for (int j = 0; j < 4; j++) {
        mx = fmaxf(mx, fmaxf(fmaxf(v[j].x, v[j].y), fmaxf(v[j].z, v[j].w)));
    }

    unsigned int m = 0;
    if (mx >= TG) {
#pragma unroll
        for (int j = 0; j < 4; j++) {
            m |= (v[j].x >= TG) ? (1u << (4 * j + 0)) : 0u;
            m |= (v[j].y >= TG) ? (1u << (4 * j + 1)) : 0u;
            m |= (v[j].z >= TG) ? (1u << (4 * j + 2)) : 0u;
            m |= (v[j].w >= TG) ? (1u << (4 * j + 3)) : 0u;
        }
    }

    const int nh = __popc(m);
    if (__ballot_sync(0xFFFFFFFFu, nh) != 0) {
        int pre = nh;
#pragma unroll
        for (int off = 1; off < 32; off <<= 1) {
            int y = __shfl_up_sync(0xFFFFFFFFu, pre, off);
            if (lane >= off) pre += y;
        }
        const int tot = __shfl_sync(0xFFFFFFFFu, pre, 31);
        int wbase = 0;
        if (lane == 31) wbase = atomicAdd(&sh_cnt, tot);
        wbase = __shfl_sync(0xFFFFFFFFu, wbase, 31);

        int pos = wbase + pre - nh;
        if (nh) {
#pragma unroll
            for (int j = 0; j < 4; j++) {
                const int i4 = tid + j * 25600;
                const float f0 = v[j].x, f1 = v[j].y, f2 = v[j].z, f3 = v[j].w;
#pragma unroll
                for (int k = 0; k < 4; k++) {
                    if (m & (1u << (4 * j + k))) {
                        if (pos < STAGE) {
                            const float f = (k == 0) ? f0 : (k == 1) ? f1 : (k == 2) ? f2 : f3;
                            const unsigned int o = ordf(f);
                            const unsigned int idx = (unsigned int)(i4 * 4 + k);
                            stage[pos] = ((ull)o << 32) | (ull)(0xFFFFFFFFu - idx);
                        } else {
                            sh_ovf = 1;
                        }
                        pos++;
                    }
                }
            }
        }
    }
    __syncthreads();

    if (t == 0) {
        int add = sh_cnt + (sh_ovf ? 1000000 : 0);   // poison on overflow
        sh_base = add ? atomicAdd(&g_count[b], add) : 0;
    }
    __syncthreads();

    const int cnt = min(sh_cnt, STAGE);
    const int base = sh_base;
    for (int i = t; i < cnt; i += TPB) {
        const int p = base + i;
        if (p < CAP) g_cand[b * CAP + p] = stage[i];
    }
}

// ---------------------------------------------------------------------------
// Kernel B: per-image select. grid 32 x 1024.
// Counting sort: histogram -> suffix scan -> unordered scatter (groups each
// bucket contiguously) -> PARALLEL rank-within-bucket (replaces the serial
// insertion sort that was the 12.5us bottleneck) -> final scatter -> emit.
// ---------------------------------------------------------------------------
__global__ void __launch_bounds__(1024) k_select(const float* __restrict__ preds,
                                                 float* __restrict__ out) {
    __shared__ __align__(16) ull skeys[2048];        // 16 KB raw keys / final sorted
    __shared__ __align__(16) ull ssort[2048];        // 16 KB bucket-grouped keys
    __shared__ unsigned int hist[NB2];               //  8 KB
    __shared__ unsigned int start[NB2];              //  8 KB
    __shared__ unsigned int part[1024];              //  4 KB (fallback only)
    __shared__ unsigned int wtmp[32], wtmp2[32];
    __shared__ unsigned int sh_mn, sh_sh;
    __shared__ int sh_T, sh_c2;

    const int b = blockIdx.x;
    const int t = threadIdx.x;
    const int lane = t & 31;
    const int wid = t >> 5;

    const float* chan = preds + (size_t)b * 3 * HW_;

    int M = g_count[b];

    // ============ FALLBACK (never taken for valid fast path) ============
    if (M < TOPK_ || M > CAP) {
        for (int i = t; i < NB2; i += 1024) hist[i] = 0u;
        if (t == 0) { sh_T = 0; sh_c2 = 0; }
        __syncthreads();

        const float4* sc = (const float4*)chan;
        for (int i = t; i < HW_ / 4; i += 1024) {
            const float4 w = sc[i];
            atomicAdd(&hist[ordf(w.x) >> 21], 1u);
            atomicAdd(&hist[ordf(w.y) >> 21], 1u);
            atomicAdd(&hist[ordf(w.z) >> 21], 1u);
            atomicAdd(&hist[ordf(w.w) >> 21], 1u);
        }
        __syncthreads();

        const unsigned int p2 = hist[2 * t] + hist[2 * t + 1];
        part[t] = p2;
        __syncthreads();
        for (int off = 1; off < 1024; off <<= 1) {
            unsigned int vv = (t + off < 1024) ? part[t + off] : 0u;
            __syncthreads();
            part[t] += vv;
            __syncthreads();
        }
        unsigned int acc = part[t] - p2;
        for (int j = 1; j >= 0; j--) {
            acc += hist[2 * t + j];
            if (acc >= (unsigned)TOPK_) { atomicMax(&sh_T, 2 * t + j); break; }
        }
        __syncthreads();
        const unsigned int T = (unsigned int)sh_T;

        for (int i = t; i < HW_ / 4; i += 1024) {
            const float4 w = sc[i];
            const float f[4] = {w.x, w.y, w.z, w.w};
#pragma unroll
            for (int k = 0; k < 4; k++) {
                const unsigned int o = ordf(f[k]);
                if ((o >> 21) >= T) {
                    const int p = atomicAdd(&sh_c2, 1);
                    if (p < CAP) {
                        const unsigned int idx = (unsigned int)(i * 4 + k);
                        g_cand[b * CAP + p] = ((ull)o << 32) | (ull)(0xFFFFFFFFu - idx);
                    }
                }
            }
        }
        __syncthreads();
        M = min(sh_c2, CAP);
    }
    M = min(M, CAP);

    const bool inshared = (M <= 2048);
    ull* kraw = inshared ? skeys : &g_cand[b * CAP];     // raw keys
    ull* kgrp = inshared ? ssort : &g_sorted[b * CAP];   // bucket-grouped
    // final sorted destination: reuse raw buffer (raw dead after grouping)
    ull* kfin = kraw;

    // ---- load keys to shared once + min/max (fused) ----
    unsigned int lmin = 0xFFFFFFFFu, lmax = 0u;
    for (int i = t; i < M; i += 1024) {
        const ull key = g_cand[b * CAP + i];
        if (inshared) skeys[i] = key;
        const unsigned int h = (unsigned int)(key >> 32);
        lmin = min(lmin, h);
        lmax = max(lmax, h);
    }
#pragma unroll
    for (int off = 16; off > 0; off >>= 1) {
        lmin = min(lmin, __shfl_down_sync(0xFFFFFFFFu, lmin, off));
        lmax = max(lmax, __shfl_down_sync(0xFFFFFFFFu, lmax, off));
    }
    if (lane == 0) { wtmp[wid] = lmin; wtmp2[wid] = lmax; }
    hist[2 * t] = 0u; hist[2 * t + 1] = 0u;
    __syncthreads();
    if (wid == 0) {
        unsigned int mn = wtmp[lane], mx = wtmp2[lane];
#pragma unroll
        for (int off = 16; off > 0; off >>= 1) {
            mn = min(mn, __shfl_down_sync(0xFFFFFFFFu, mn, off));
            mx = max(mx, __shfl_down_sync(0xFFFFFFFFu, mx, off));
        }
        if (lane == 0) {
            const unsigned int range = mx - mn;
            const int bits = 32 - __clz(range | 1u);
            sh_sh = (bits > 11) ? (unsigned)(bits - 11) : 0u;
            sh_mn = mn;
        }
    }
    __syncthreads();
    const unsigned int mn = sh_mn, shf = sh_sh;

    // ---- histogram ----
    for (int i = t; i < M; i += 1024) {
        const unsigned int h = (unsigned int)(kraw[i] >> 32);
        atomicAdd(&hist[(h - mn) >> shf], 1u);
    }
    __syncthreads();

    // ---- hierarchical suffix scan over 2048 buckets ----
    const unsigned int h0 = hist[2 * t], h1 = hist[2 * t + 1];
    const unsigned int s_own = h0 + h1;
    unsigned int s_incl = s_own;
#pragma unroll
    for (int off = 1; off < 32; off <<= 1) {
        unsigned int y = __shfl_down_sync(0xFFFFFFFFu, s_incl, off);
        if (lane + off < 32) s_incl += y;
    }
    if (lane == 0) wtmp[wid] = s_incl;
    __syncthreads();
    if (wid == 0) {
        unsigned int wv = wtmp[lane];
        unsigned int wincl = wv;
#pragma unroll
        for (int off = 1; off < 32; off <<= 1) {
            unsigned int y = __shfl_down_sync(0xFFFFFFFFu, wincl, off);
            if (lane + off < 32) wincl += y;
        }
        wtmp[lane] = wincl - wv;
    }
    __syncthreads();
    {
        const unsigned int above = wtmp[wid] + (s_incl - s_own);
        start[2 * t + 1] = above;
        start[2 * t]     = above + h1;
        hist[2 * t] = 0u; hist[2 * t + 1] = 0u;   // -> intra-bucket counters
    }
    __syncthreads();

    // ---- scatter 1: group each bucket contiguously (unordered within) ----
    for (int i = t; i < M; i += 1024) {
        const ull key = kraw[i];
        const unsigned int bk = ((unsigned int)(key >> 32) - mn) >> shf;
        const unsigned int p = start[bk] + atomicAdd(&hist[bk], 1u);
        kgrp[p] = key;
    }
    __syncthreads();
    // hist[bk] now holds bucket count c

    // ---- parallel rank-within-bucket + final scatter ----
    // Every element scans only its own bucket (c ~ 1-25 keys) -> rank; keys
    // unique so start+rank is a permutation. Fully parallel across elements.
    for (int p = t; p < M; p += 1024) {
        const ull key = kgrp[p];
        const unsigned int bk = ((unsigned int)(key >> 32) - mn) >> shf;
        const unsigned int st = start[bk];
        const unsigned int c  = hist[bk];
        unsigned int r = 0;
        for (unsigned int q = 0; q < c; q++) r += (kgrp[st + q] > key);
        kfin[st + r] = key;
    }
    __syncthreads();

    // ---- emit ----
    const float* ph = chan + HW_;
    const float* pw = ph + HW_;
    float* boxes  = out;                              // [B, K, 4]
    float* scores = out + (size_t)B_ * TOPK_ * 4;     // [B, K]
    float* keep   = scores + (size_t)B_ * TOPK_;      // [B, K]

    if (t < TOPK_) {
        const ull kk = kfin[t];
        const unsigned int o = (unsigned int)(kk >> 32);
        const unsigned int u = (o & 0x80000000u) ? (o ^ 0x80000000u) : ~o;
        const float score = __uint_as_float(u);
        const unsigned int idx = 0xFFFFFFFFu - (unsigned int)(kk & 0xFFFFFFFFull);

        const float h = fmaxf(ph[idx], 1e-6f) * (float)H_;
        const float w = fmaxf(pw[idx], 1e-6f) * (float)W_;
        const float cx = (float)(idx % W_);
        const float cy = (float)(idx / W_);

        float* bx = boxes + ((size_t)b * TOPK_ + t) * 4;
        bx[0] = cx - 0.5f * w;
        bx[1] = cy - 0.5f * h;
        bx[2] = cx + 0.5f * w;
        bx[3] = cy + 0.5f * h;
        scores[b * TOPK_ + t] = score;
        keep[b * TOPK_ + t]   = 1.0f;
    }

    if (t == 0) g_count[b] = 0;   // reset for next graph replay
}

// ---------------------------------------------------------------------------
extern "C" void kernel_launch(void* const* d_in, const int* in_sizes, int n_in,
                              void* d_out, int out_size) {
    const float* preds = (const float*)d_in[0];
    float* out = (float*)d_out;

    dim3 gp(BX, B_);
    k_pass<<<gp, TPB>>>(preds);
    k_select<<<B_, 1024>>>(preds, out);
}